// round 1
// baseline (speedup 1.0000x reference)
#include <cuda_runtime.h>
#include <math.h>

#define Hh 160
#define Ww 480
#define HW 76800
#define NP 120000

// ---------------- scratch (no allocations allowed) ----------------
__device__ int    d_win[3][HW];
__device__ float4 d_G0[9][16];    // folded red_w0 -> tap weights   [k][c/4]
__device__ float4 d_G1[9][32];    // folded red_w1 -> tap weights
__device__ float4 d_Wimg[9][64];  // sb_w[0:256]  transposed to [k][c/4]
__device__ float4 d_Wpt[9][64];   // sb_w[256:512] transposed to [k][o/4]
__device__ float  d_cb[9];        // folded bias constants per tap
__device__ float  d_t[9][HW];     // per-tap channel-reduced maps
__device__ __align__(16) float d_att[HW];

// ---------------- K0: fold 1x1 conv weights into the 3x3 taps ----------------
__global__ void k_prep(const float* __restrict__ rw0, const float* __restrict__ rb0,
                       const float* __restrict__ rw1, const float* __restrict__ rb1,
                       const float* __restrict__ sbw) {
    int k = blockIdx.x;      // tap 0..8
    int tid = threadIdx.x;   // 0..255
    ((float*)d_Wimg)[k * 256 + tid] = sbw[tid * 9 + k];
    ((float*)d_Wpt)[k * 256 + tid]  = sbw[(256 + tid) * 9 + k];
    if (tid < 64) {
        float s = 0.f;
        for (int o = 0; o < 256; o++) s += rw0[o * 64 + tid] * sbw[(256 + o) * 9 + k];
        ((float*)d_G0)[k * 64 + tid] = s;
    }
    if (tid < 128) {
        float s = 0.f;
        for (int o = 0; o < 256; o++) s += rw1[o * 128 + tid] * sbw[(256 + o) * 9 + k];
        ((float*)d_G1)[k * 128 + tid] = s;
    }
    if (tid == 0) {
        float s = 0.f;
        for (int o = 0; o < 256; o++) s += (rb0[o] + rb1[o]) * sbw[(256 + o) * 9 + k];
        d_cb[k] = s;
    }
}

// ---------------- K1: init winner maps ----------------
__global__ void k_init() {
    int i = blockIdx.x * blockDim.x + threadIdx.x;
    if (i < 3 * HW) ((int*)d_win)[i] = -1;
}

// ---------------- K2: scatter, last-write-wins == max point index ----------------
__global__ void k_scatter(const int* __restrict__ g0, const int* __restrict__ g1,
                          const int* __restrict__ g2) {
    int i = blockIdx.x * blockDim.x + threadIdx.x;
    if (i >= 3 * NP) return;
    int lvl = i / NP;
    int p = i - lvl * NP;
    const int* g = (lvl == 0) ? g0 : ((lvl == 1) ? g1 : g2);
    int x = g[2 * p];
    int y = g[2 * p + 1];
    if (x >= 0 && x < Ww && y >= 0 && y < Hh)
        atomicMax(&d_win[lvl][y * Ww + x], p);
}

// ---------------- K3: per-pixel 9-tap channel reductions ----------------
__global__ void __launch_bounds__(256) k_main(const float* __restrict__ img,
                                              const float* __restrict__ seg,
                                              const float* __restrict__ vf0,
                                              const float* __restrict__ vf1,
                                              const float* __restrict__ vf2) {
    __shared__ float4 sWimg[9][64];
    __shared__ float4 sWpt[9][64];
    __shared__ float4 sG0[9][16];
    __shared__ float4 sG1[9][32];
    __shared__ float  scb[9];

    int tid = threadIdx.x;
    for (int i = tid; i < 9 * 64; i += 256) {
        ((float4*)sWimg)[i] = ((const float4*)d_Wimg)[i];
        ((float4*)sWpt)[i]  = ((const float4*)d_Wpt)[i];
    }
    for (int i = tid; i < 9 * 16; i += 256) ((float4*)sG0)[i] = ((const float4*)d_G0)[i];
    for (int i = tid; i < 9 * 32; i += 256) ((float4*)sG1)[i] = ((const float4*)d_G1)[i];
    if (tid < 9) scb[tid] = d_cb[tid];
    __syncthreads();

    int pix = blockIdx.x * 256 + tid;
    float s = seg[HW + pix];

    float acc[9], accI[9];
#pragma unroll
    for (int k = 0; k < 9; k++) { acc[k] = scb[k]; accI[k] = 0.f; }

    // image channels (enhanced = img * seg; seg factored out of the dot)
    const float* ip = img + pix;
#pragma unroll 2
    for (int c4 = 0; c4 < 64; c4++) {
        float a0 = ip[(size_t)(4 * c4 + 0) * HW];
        float a1 = ip[(size_t)(4 * c4 + 1) * HW];
        float a2 = ip[(size_t)(4 * c4 + 2) * HW];
        float a3 = ip[(size_t)(4 * c4 + 3) * HW];
#pragma unroll
        for (int k = 0; k < 9; k++) {
            float4 w = sWimg[k][c4];
            accI[k] += a0 * w.x + a1 * w.y + a2 * w.z + a3 * w.w;
        }
    }

    // level 0: gathered vf0 dotted with folded weights G0
    int p0 = d_win[0][pix];
    if (p0 >= 0) {
        const float4* v = (const float4*)(vf0 + (size_t)p0 * 64);
#pragma unroll 2
        for (int c4 = 0; c4 < 16; c4++) {
            float4 a = v[c4];
#pragma unroll
            for (int k = 0; k < 9; k++) {
                float4 w = sG0[k][c4];
                acc[k] += a.x * w.x + a.y * w.y + a.z * w.z + a.w * w.w;
            }
        }
    }
    // level 1
    int p1 = d_win[1][pix];
    if (p1 >= 0) {
        const float4* v = (const float4*)(vf1 + (size_t)p1 * 128);
#pragma unroll 2
        for (int c4 = 0; c4 < 32; c4++) {
            float4 a = v[c4];
#pragma unroll
            for (int k = 0; k < 9; k++) {
                float4 w = sG1[k][c4];
                acc[k] += a.x * w.x + a.y * w.y + a.z * w.z + a.w * w.w;
            }
        }
    }
    // level 2 (identity channels, weights are the raw pt-tap weights)
    int p2 = d_win[2][pix];
    if (p2 >= 0) {
        const float4* v = (const float4*)(vf2 + (size_t)p2 * 256);
#pragma unroll 2
        for (int c4 = 0; c4 < 64; c4++) {
            float4 a = v[c4];
#pragma unroll
            for (int k = 0; k < 9; k++) {
                float4 w = sWpt[k][c4];
                acc[k] += a.x * w.x + a.y * w.y + a.z * w.z + a.w * w.w;
            }
        }
    }

#pragma unroll
    for (int k = 0; k < 9; k++) d_t[k][pix] = acc[k] + s * accI[k];
}

// ---------------- K4a: combine shifted tap maps -> sigmoid -> fold seg gate ----------------
__global__ void k_att(const float* __restrict__ seg, const float* __restrict__ sbb) {
    int pix = blockIdx.x * 256 + threadIdx.x;
    int y = pix / Ww;
    int x = pix - y * Ww;
    float sum = sbb[0];
#pragma unroll
    for (int ky = 0; ky < 3; ky++) {
        int yy = y + ky - 1;
        if (yy < 0 || yy >= Hh) continue;
#pragma unroll
        for (int kx = 0; kx < 3; kx++) {
            int xx = x + kx - 1;
            if (xx < 0 || xx >= Ww) continue;
            sum += d_t[ky * 3 + kx][yy * Ww + xx];
        }
    }
    float att = 1.f / (1.f + expf(-sum));
    d_att[pix] = att * seg[HW + pix];
}

// ---------------- K4b: out = img * (seg * attention), pure stream ----------------
__global__ void k_out(const float4* __restrict__ img, float4* __restrict__ out) {
    int i = blockIdx.x * 256 + threadIdx.x;  // float4 index, total 256*HW/4
    int pix4 = i % (HW / 4);
    float4 a = *(const float4*)(&d_att[pix4 * 4]);
    float4 im = img[i];
    float4 o;
    o.x = im.x * a.x;
    o.y = im.y * a.y;
    o.z = im.z * a.z;
    o.w = im.w * a.w;
    out[i] = o;
}

extern "C" void kernel_launch(void* const* d_in, const int* in_sizes, int n_in,
                              void* d_out, int out_size) {
    const float* img = (const float*)d_in[0];
    const float* seg = (const float*)d_in[1];

    // metadata order robustness: dict order interleaves voxel_feat{i}, img_grid{i};
    // signature order groups them. Detect via element counts.
    int iv0, iv1, iv2, ig0, ig1, ig2;
    if (in_sizes[3] == 2 * NP) { iv0 = 2; ig0 = 3; iv1 = 4; ig1 = 5; iv2 = 6; ig2 = 7; }
    else                       { iv0 = 2; iv1 = 3; iv2 = 4; ig0 = 5; ig1 = 6; ig2 = 7; }

    const float* vf0 = (const float*)d_in[iv0];
    const float* vf1 = (const float*)d_in[iv1];
    const float* vf2 = (const float*)d_in[iv2];
    const int*   g0  = (const int*)d_in[ig0];
    const int*   g1  = (const int*)d_in[ig1];
    const int*   g2  = (const int*)d_in[ig2];
    const float* rw0 = (const float*)d_in[8];
    const float* rb0 = (const float*)d_in[9];
    const float* rw1 = (const float*)d_in[10];
    const float* rb1 = (const float*)d_in[11];
    const float* sbw = (const float*)d_in[12];
    const float* sbb = (const float*)d_in[13];

    k_prep<<<9, 256>>>(rw0, rb0, rw1, rb1, sbw);
    k_init<<<(3 * HW + 255) / 256, 256>>>();
    k_scatter<<<(3 * NP + 255) / 256, 256>>>(g0, g1, g2);
    k_main<<<HW / 256, 256>>>(img, seg, vf0, vf1, vf2);
    k_att<<<HW / 256, 256>>>(seg, sbb);
    k_out<<<(256 * HW / 4) / 256, 256>>>((const float4*)img, (float4*)d_out);
}